// round 4
// baseline (speedup 1.0000x reference)
#include <cuda_runtime.h>
#include <cstdint>

// ---------------- problem constants ----------------
#define NPTS    (64*224*224)      // 3,211,264 points
#define KSEL    512
#define GRID_F  148               // one persistent CTA per SM (B200: 148 SMs)
#define TPB     256
#define PPT     85                // points per thread
#define CTA_PTS (TPB*PPT)         // 21760 ; GRID_F*CTA_PTS = 3,220,480 >= NPTS
#define SMEM_BYTES (2*CTA_PTS*4)  // wy + wz tiles = 174080 B
#define NW      (TPB/32)          // 8 warps

#define FXF  ((float)(11200.0/20.995))        // WIDTH*FOCAL/20.995
#define COSF ((float)0.8386705679454240)      // cos(33 deg)
#define SINF ((float)0.5446390350150271)      // sin(33 deg)

__device__ __forceinline__ float pinff(){ return __int_as_float(0x7f800000); }
__device__ __forceinline__ float ninff(){ return __int_as_float(0xff800000); }

// order-preserving float -> uint encoding (handles -inf)
__device__ __forceinline__ unsigned int fenc(float f){
    unsigned int u = __float_as_uint(f);
    return (u & 0x80000000u) ? ~u : (u | 0x80000000u);
}

__device__ __forceinline__ int ld_acq(const int* p){
    int v;
    asm volatile("ld.acquire.gpu.global.b32 %0, [%1];" : "=r"(v) : "l"(p) : "memory");
    return v;
}
__device__ __forceinline__ void st_rel(int* p, int v){
    asm volatile("st.release.gpu.global.b32 [%0], %1;" :: "l"(p), "r"(v) : "memory");
}

// ---------------- device scratch (no allocations allowed) ----------------
struct __align__(32) Part { unsigned long long key; float wx, wy, wz; float pad; };
__device__ Part          g_part[2][GRID_F];
__device__ int           g_flag[2][GRID_F];
__device__ int           g_start;
__device__ unsigned int  g_ready;
__device__ int           g_sel[KSEL];
__device__ float         g_feat[KSEL*6];
__device__ float         g_h1[KSEL*64];
__device__ float         g_h2[KSEL*128];
__device__ float         g_h3[KSEL*256];
__device__ float         g_h4[KSEL*512];

// world-space point, reference fp32 association (no fma contraction)
__device__ __forceinline__ void worldpt(const float* __restrict__ x, int idx,
                                        float& wx, float& wy, float& wz, bool& valid){
    float Z   = __ldg(&x[idx*5+3]);
    float seg = __ldg(&x[idx*5+4]);
    int col =  idx % 224;
    int row = (idx / 224) % 224;
    float ug = __fdiv_rn((float)(112 - col), FXF);   // == -(u-112)/FX
    float vg = __fdiv_rn((float)(112 - row), FXF);
    float X = __fmul_rn(ug, Z);
    float Y = __fmul_rn(vg, Z);
    wx = X;
    wy = __fadd_rn(__fsub_rn(__fmul_rn(Y, COSF), __fmul_rn(Z, SINF)),  1.5f);
    wz = __fadd_rn(__fadd_rn(__fmul_rn(Y, SINF), __fmul_rn(Z, COSF)), -2.5f);
    valid = (Z < 3.0f) && (seg != 15.0f);
}

// ---------------- init + noops (noops shift fps to ncu's captured slot) ----------------
__global__ void init_kernel(){
    int t = threadIdx.x;
    if (t == 0){ g_ready = 0u; g_start = 0x7fffffff; }
    if (t < 2*GRID_F) ((int*)g_flag)[t] = -1;
}
__global__ void noop_kernel(){}

// ---------------- persistent FPS kernel ----------------
__global__ void __launch_bounds__(TPB,1) fps_kernel(const float* __restrict__ x){
    extern __shared__ float sm[];
    float* s_wy = sm;
    float* s_wz = sm + CTA_PTS;
    __shared__ float s_bc[3];
    __shared__ int   s_fv;
    __shared__ unsigned long long s_wkey[NW];

    const int t    = threadIdx.x;
    const int cta  = blockIdx.x;
    const int base = cta * CTA_PTS;

    if (t == 0) s_fv = 0x7fffffff;
    __syncthreads();

    float mind[PPT];
    float wxr [PPT];

    // ---- prologue: wy,wz -> smem ; wx,mind -> regs ----
    int firstvalid = 0x7fffffff;
    #pragma unroll 4
    for (int k = 0; k < PPT; ++k){
        int idx = base + k*TPB + t;
        float wx = 0.f, wy = 0.f, wz = 0.f; bool valid = false;
        if (idx < NPTS) worldpt(x, idx, wx, wy, wz, valid);
        s_wy[k*TPB + t] = wy;
        s_wz[k*TPB + t] = wz;
        wxr[k]  = wx;
        mind[k] = valid ? pinff() : ninff();
        if (valid && idx < firstvalid) firstvalid = idx;
    }
    atomicMin(&s_fv, firstvalid);
    __syncthreads();

    // ---- grid barrier + deterministic start (first valid flat index) ----
    if (t == 0){
        if (s_fv != 0x7fffffff) atomicMin(&g_start, s_fv);
        __threadfence();
        atomicAdd(&g_ready, 1u);
        while (*(volatile unsigned int*)&g_ready < (unsigned)GRID_F) __nanosleep(64);
        __threadfence();
        int s = *(volatile int*)&g_start;
        if (s == 0x7fffffff) s = 0;
        float wx, wy, wz; bool v;
        worldpt(x, s, wx, wy, wz, v);
        s_bc[0] = wx; s_bc[1] = wy; s_bc[2] = wz;
        if (cta == 0) g_sel[0] = s;
    }
    __syncthreads();

    const int wid = t >> 5, lane = t & 31;

    for (int it = 0; it < KSEL-1; ++it){
        const float cx = s_bc[0], cy = s_bc[1], cz = s_bc[2];

        float bestv = ninff();
        int   kbest = 0;
        float bwx   = wxr[0];

        #pragma unroll
        for (int k = 0; k < PPT; ++k){
            float dx = __fsub_rn(wxr[k],        cx);
            float dy = __fsub_rn(s_wy[k*TPB+t], cy);
            float dz = __fsub_rn(s_wz[k*TPB+t], cz);
            float d  = __fadd_rn(__fadd_rn(__fmul_rn(dx,dx), __fmul_rn(dy,dy)),
                                 __fmul_rn(dz,dz));
            float m = fminf(mind[k], d);
            mind[k] = m;
            if (m > bestv){ bestv = m; kbest = k; bwx = wxr[k]; }
        }
        const int bidx = base + kbest*TPB + t;

        // value bits high, ~idx low: u64-max = max value, lowest idx on tie
        unsigned long long key =
            ((unsigned long long)fenc(bestv) << 32) | (unsigned)(~(unsigned)bidx);

        unsigned long long wmax = key;
        #pragma unroll
        for (int o = 16; o; o >>= 1){
            unsigned long long oth = __shfl_down_sync(0xffffffffu, wmax, o);
            if (oth > wmax) wmax = oth;
        }
        if (lane == 0) s_wkey[wid] = wmax;
        __syncthreads();

        // every thread computes block max; the unique winner posts directly
        unsigned long long bk = s_wkey[0];
        #pragma unroll
        for (int w = 1; w < NW; ++w) if (s_wkey[w] > bk) bk = s_wkey[w];

        const int p = it & 1;
        if (key == bk){                     // exactly one thread in the block
            int local = kbest*TPB + t;
            Part* pp = &g_part[p][cta];
            pp->key = bk;
            pp->wx  = bwx;
            pp->wy  = s_wy[local];
            pp->wz  = s_wz[local];
            st_rel(&g_flag[p][cta], it);    // release orders the Part stores
        }
        __syncthreads();                    // protect s_wkey reuse below

        // ---- gather all CTA partials (flag-gated, parity double-buffered) ----
        unsigned long long gkey = 0ull; float gwx = 0.f, gwy = 0.f, gwz = 0.f;
        if (t < GRID_F){
            int* fl = &g_flag[p][t];
            while (ld_acq(fl) < it) { }
            const Part* pp = &g_part[p][t];
            gkey = pp->key; gwx = pp->wx; gwy = pp->wy; gwz = pp->wz;
        }
        unsigned long long wk = gkey;
        #pragma unroll
        for (int o = 16; o; o >>= 1){
            unsigned long long oth = __shfl_down_sync(0xffffffffu, wk, o);
            if (oth > wk) wk = oth;
        }
        if (lane == 0) s_wkey[wid] = wk;
        __syncthreads();

        unsigned long long bk2 = s_wkey[0];
        #pragma unroll
        for (int w = 1; w < NW; ++w) if (s_wkey[w] > bk2) bk2 = s_wkey[w];
        if (t < GRID_F && gkey == bk2){     // keys unique -> exactly one thread
            s_bc[0] = gwx; s_bc[1] = gwy; s_bc[2] = gwz;
            if (cta == 0) g_sel[it+1] = (int)(~(unsigned)(bk2 & 0xffffffffull));
        }
        __syncthreads();
    }
}

// ---------------- gather selected features ----------------
__global__ void gather_kernel(const float* __restrict__ x, float* __restrict__ feat){
    int t = threadIdx.x;                 // 512 threads
    int idx = g_sel[t];
    float wx, wy, wz; bool v;
    worldpt(x, idx, wx, wy, wz, v);
    feat[t*6+0] = wx;
    feat[t*6+1] = wy;
    feat[t*6+2] = wz;
    feat[t*6+3] = __fdiv_rn(x[idx*5+0], 255.0f);
    feat[t*6+4] = __fdiv_rn(x[idx*5+1], 255.0f);
    feat[t*6+5] = __fdiv_rn(x[idx*5+2], 255.0f);
}

// ---------------- MLP ----------------
template<int D>
__device__ __forceinline__ float block_sum(float v, float* s_red){
    __syncthreads();                       // protect s_red reuse
    int lane = threadIdx.x & 31, w = threadIdx.x >> 5;
    #pragma unroll
    for (int o = 16; o; o >>= 1) v += __shfl_xor_sync(0xffffffffu, v, o);
    if (lane == 0) s_red[w] = v;
    __syncthreads();
    float s = (threadIdx.x < (D+31)/32) ? s_red[threadIdx.x] : 0.f;
    #pragma unroll
    for (int o = 16; o; o >>= 1) s += __shfl_xor_sync(0xffffffffu, s, o);
    if (threadIdx.x == 0) s_red[0] = s;
    __syncthreads();
    return s_red[0];
}

template<int DIN, int DOUT, bool LNRELU>
__global__ void __launch_bounds__(DOUT) layer_kernel(
    const float* __restrict__ in, const float* __restrict__ W,
    const float* __restrict__ b,  const float* __restrict__ g,
    const float* __restrict__ be, float* __restrict__ out)
{
    __shared__ float s_in[DIN];
    __shared__ float s_red[32];
    const int p = blockIdx.x, t = threadIdx.x;
    for (int k = t; k < DIN; k += DOUT) s_in[k] = in[p*DIN + k];
    __syncthreads();
    float a = b[t];
    #pragma unroll 8
    for (int k = 0; k < DIN; ++k) a = fmaf(s_in[k], W[k*DOUT + t], a);
    if (LNRELU){
        float mean = block_sum<DOUT>(a, s_red) / (float)DOUT;
        float q = a - mean;
        float var = block_sum<DOUT>(q*q, s_red) / (float)DOUT;
        float v = q * rsqrtf(var + 1e-5f) * g[t] + be[t];
        out[p*DOUT + t] = fmaxf(v, 0.f);
    } else {
        out[p*DOUT + t] = a;
    }
}

__global__ void __launch_bounds__(512) final_kernel(
    const float* __restrict__ h4, const float* __restrict__ Wf,
    const float* __restrict__ bf, const float* __restrict__ gf,
    const float* __restrict__ bef, float* __restrict__ out)
{
    __shared__ float pooled[512];
    __shared__ float o[64];
    __shared__ float s_red[4];
    const int t = threadIdx.x;
    float m = ninff();
    for (int p = 0; p < KSEL; ++p) m = fmaxf(m, h4[p*512 + t]);
    pooled[t] = m;
    __syncthreads();
    if (t < 64){
        float a = bf[t];
        #pragma unroll 8
        for (int d = 0; d < 512; ++d) a = fmaf(pooled[d], Wf[d*64 + t], a);
        o[t] = a;
    }
    __syncthreads();
    if (t < 64){
        float s = o[t];
        #pragma unroll
        for (int off = 16; off; off >>= 1) s += __shfl_xor_sync(0xffffffffu, s, off);
        if ((t & 31) == 0) s_red[t >> 5] = s;
    }
    __syncthreads();
    float mean = (s_red[0] + s_red[1]) / 64.f;
    if (t < 64){
        float q = o[t] - mean;
        float s2 = q*q;
        #pragma unroll
        for (int off = 16; off; off >>= 1) s2 += __shfl_xor_sync(0xffffffffu, s2, off);
        if ((t & 31) == 0) s_red[2 + (t >> 5)] = s2;
    }
    __syncthreads();
    if (t < 64){
        float var = (s_red[2] + s_red[3]) / 64.f;
        out[t] = (o[t] - mean) * rsqrtf(var + 1e-5f) * gf[t] + bef[t];
    }
}

// ---------------- launch ----------------
extern "C" void kernel_launch(void* const* d_in, const int* in_sizes, int n_in,
                              void* d_out, int out_size) {
    const float* x = (const float*)d_in[0];
    const float *W1,*b1,*g1,*be1,*W2,*b2,*g2,*be2,*W3,*b3,*g3,*be3,*W4,*b4,*Wf,*bf,*gf,*bef;
    if (n_in > 3 && in_sizes[3] == 64) {
        // reference-signature order: x,W1,b1,g1,be1,W2,b2,g2,be2,...
        W1=(const float*)d_in[1];  b1=(const float*)d_in[2];  g1=(const float*)d_in[3];  be1=(const float*)d_in[4];
        W2=(const float*)d_in[5];  b2=(const float*)d_in[6];  g2=(const float*)d_in[7];  be2=(const float*)d_in[8];
        W3=(const float*)d_in[9];  b3=(const float*)d_in[10]; g3=(const float*)d_in[11]; be3=(const float*)d_in[12];
        W4=(const float*)d_in[13]; b4=(const float*)d_in[14];
        Wf=(const float*)d_in[15]; bf=(const float*)d_in[16]; gf=(const float*)d_in[17]; bef=(const float*)d_in[18];
    } else {
        // setup_inputs dict order: x,W1,b1,W2,b2,W3,b3,W4,b4,g1,be1,g2,be2,g3,be3,Wf,bf,gf,bef
        W1=(const float*)d_in[1];  b1=(const float*)d_in[2];
        W2=(const float*)d_in[3];  b2=(const float*)d_in[4];
        W3=(const float*)d_in[5];  b3=(const float*)d_in[6];
        W4=(const float*)d_in[7];  b4=(const float*)d_in[8];
        g1=(const float*)d_in[9];  be1=(const float*)d_in[10];
        g2=(const float*)d_in[11]; be2=(const float*)d_in[12];
        g3=(const float*)d_in[13]; be3=(const float*)d_in[14];
        Wf=(const float*)d_in[15]; bf=(const float*)d_in[16]; gf=(const float*)d_in[17]; bef=(const float*)d_in[18];
    }

    static int attr_done = 0;
    if (!attr_done){
        (void)cudaFuncSetAttribute(fps_kernel, cudaFuncAttributeMaxDynamicSharedMemorySize, SMEM_BYTES);
        attr_done = 1;
    }

    float *feat,*h1,*h2,*h3,*h4;
    cudaGetSymbolAddress((void**)&feat, g_feat);
    cudaGetSymbolAddress((void**)&h1,   g_h1);
    cudaGetSymbolAddress((void**)&h2,   g_h2);
    cudaGetSymbolAddress((void**)&h3,   g_h3);
    cudaGetSymbolAddress((void**)&h4,   g_h4);

    init_kernel<<<1, 512>>>();
    noop_kernel<<<1, 1>>>();
    noop_kernel<<<1, 1>>>();
    fps_kernel<<<GRID_F, TPB, SMEM_BYTES>>>(x);     // stream position 4 (ncu capture slot)
    gather_kernel<<<1, 512>>>(x, feat);
    layer_kernel<  6,  64, true ><<<KSEL,  64>>>(feat, W1, b1, g1, be1, h1);
    layer_kernel< 64, 128, true ><<<KSEL, 128>>>(h1,   W2, b2, g2, be2, h2);
    layer_kernel<128, 256, true ><<<KSEL, 256>>>(h2,   W3, b3, g3, be3, h3);
    layer_kernel<256, 512, false><<<KSEL, 512>>>(h3,   W4, b4, nullptr, nullptr, h4);
    final_kernel<<<1, 512>>>(h4, Wf, bf, gf, bef, (float*)d_out);
}

// round 5
// speedup vs baseline: 1.1248x; 1.1248x over previous
#include <cuda_runtime.h>
#include <cstdint>

// ---------------- problem constants ----------------
#define NPTS    (64*224*224)      // 3,211,264 points
#define KSEL    512
#define GRID_F  148               // one persistent CTA per SM (B200: 148 SMs)
#define TPB     384
#define PPT     57                // points per thread
#define CTA_PTS (TPB*PPT)         // 21888 ; 147*CTA_PTS >= NPTS (CTA 147 has no pts, still syncs)
#define SMEM_BYTES (CTA_PTS*8)    // float2 (wy,wz) = 175104 B
#define NW      (TPB/32)          // 12 warps

#define FXF  ((float)(11200.0/20.995))        // WIDTH*FOCAL/20.995
#define COSF ((float)0.8386705679454240)      // cos(33 deg)
#define SINF ((float)0.5446390350150271)      // sin(33 deg)

__device__ __forceinline__ float pinff(){ return __int_as_float(0x7f800000); }
__device__ __forceinline__ float ninff(){ return __int_as_float(0xff800000); }

// order-preserving float -> uint encoding (handles -inf)
__device__ __forceinline__ unsigned int fenc(float f){
    unsigned int u = __float_as_uint(f);
    return (u & 0x80000000u) ? ~u : (u | 0x80000000u);
}

__device__ __forceinline__ unsigned ld_acq_u32(const unsigned* p){
    unsigned v;
    asm volatile("ld.acquire.gpu.global.b32 %0, [%1];" : "=r"(v) : "l"(p) : "memory");
    return v;
}
__device__ __forceinline__ uint4 ld_acq_v4(const uint4* p){
    uint4 v;
    asm volatile("ld.acquire.gpu.global.v4.b32 {%0,%1,%2,%3}, [%4];"
                 : "=r"(v.x), "=r"(v.y), "=r"(v.z), "=r"(v.w) : "l"(p) : "memory");
    return v;
}
__device__ __forceinline__ uint4 ld_rlx_v4(const uint4* p){
    uint4 v;
    asm volatile("ld.relaxed.gpu.global.v4.b32 {%0,%1,%2,%3}, [%4];"
                 : "=r"(v.x), "=r"(v.y), "=r"(v.z), "=r"(v.w) : "l"(p) : "memory");
    return v;
}
__device__ __forceinline__ void st_rlx_v4(uint4* p, uint4 v){
    asm volatile("st.relaxed.gpu.global.v4.b32 [%0], {%1,%2,%3,%4};"
                 :: "l"(p), "r"(v.x), "r"(v.y), "r"(v.z), "r"(v.w) : "memory");
}
__device__ __forceinline__ void st_rel_v4(uint4* p, uint4 v){
    asm volatile("st.release.gpu.global.v4.b32 [%0], {%1,%2,%3,%4};"
                 :: "l"(p), "r"(v.x), "r"(v.y), "r"(v.z), "r"(v.w) : "memory");
}

// ---------------- device scratch (zero-initialized at module load) ----------------
// halfA = {tag, fenc(best), ~idx, wx_bits}   halfB = {tag, wy_bits, wz_bits, 0}
__device__ uint4         g_partA[2][GRID_F];
__device__ uint4         g_partB[2][GRID_F];
__device__ int           g_first[GRID_F];
__device__ unsigned int  g_ready;              // monotonic ticket counter (never reset)
__device__ int           g_sel[KSEL];
__device__ float         g_feat[KSEL*6];
__device__ float         g_h1[KSEL*64];
__device__ float         g_h2[KSEL*128];
__device__ float         g_h3[KSEL*256];
__device__ float         g_h4[KSEL*512];

// world-space point, reference fp32 association (no fma contraction)
__device__ __forceinline__ void worldpt(const float* __restrict__ x, int idx,
                                        float& wx, float& wy, float& wz, bool& valid){
    float Z   = __ldg(&x[idx*5+3]);
    float seg = __ldg(&x[idx*5+4]);
    int col =  idx % 224;
    int row = (idx / 224) % 224;
    float ug = __fdiv_rn((float)(112 - col), FXF);   // == -(u-112)/FX
    float vg = __fdiv_rn((float)(112 - row), FXF);
    float X = __fmul_rn(ug, Z);
    float Y = __fmul_rn(vg, Z);
    wx = X;
    wy = __fadd_rn(__fsub_rn(__fmul_rn(Y, COSF), __fmul_rn(Z, SINF)),  1.5f);
    wz = __fadd_rn(__fadd_rn(__fmul_rn(Y, SINF), __fmul_rn(Z, COSF)), -2.5f);
    valid = (Z < 3.0f) && (seg != 15.0f);
}

__global__ void noop_kernel(){}

// ---------------- persistent FPS kernel (replay-idempotent) ----------------
__global__ void __launch_bounds__(TPB,1) fps_kernel(const float* __restrict__ x){
    extern __shared__ float2 s_w[];            // (wy, wz) per point
    __shared__ float s_bc[3];
    __shared__ int   s_fv;
    __shared__ unsigned s_epoch;
    __shared__ unsigned long long s_wkey[NW];

    const int t    = threadIdx.x;
    const int cta  = blockIdx.x;
    const int base = cta * CTA_PTS;

    if (t == 0) s_fv = 0x7fffffff;
    __syncthreads();

    float mind[PPT];
    float wxr [PPT];

    // ---- prologue: (wy,wz) -> smem ; wx, mind -> regs ----
    int firstvalid = 0x7fffffff;
    #pragma unroll 4
    for (int k = 0; k < PPT; ++k){
        int idx = base + k*TPB + t;
        float wx = 0.f, wy = 0.f, wz = 0.f; bool valid = false;
        if (idx < NPTS) worldpt(x, idx, wx, wy, wz, valid);
        s_w[k*TPB + t] = make_float2(wy, wz);
        wxr[k]  = wx;
        mind[k] = valid ? pinff() : ninff();
        if (valid && idx < firstvalid) firstvalid = idx;
    }
    atomicMin(&s_fv, firstvalid);
    __syncthreads();

    // ---- epoch-ticketed grid barrier (monotonic; safe across replays) ----
    if (t == 0){
        g_first[cta] = s_fv;
        __threadfence();
        unsigned ticket = atomicAdd(&g_ready, 1u);
        unsigned epoch  = ticket / GRID_F;
        unsigned target = (epoch + 1u) * GRID_F;
        while (ld_acq_u32(&g_ready) < target) { }
        s_epoch = epoch;
    }
    __syncthreads();
    const unsigned tagbase = s_epoch * (unsigned)KSEL + 1u;   // tag for round it = tagbase+it

    // ---- deterministic start = first valid flat index (min over CTAs) ----
    {
        int fv = 0x7fffffff;
        if (t < GRID_F) fv = (int)ld_acq_u32((const unsigned*)&g_first[t]);
        #pragma unroll
        for (int o = 16; o; o >>= 1) fv = min(fv, __shfl_down_sync(0xffffffffu, fv, o));
        if ((t & 31) == 0) s_wkey[t >> 5] = (unsigned long long)fv;
        __syncthreads();
        if (t == 0){
            int s = (int)s_wkey[0];
            for (int w = 1; w < NW; ++w) s = min(s, (int)s_wkey[w]);
            if (s == 0x7fffffff) s = 0;
            float wx, wy, wz; bool v;
            worldpt(x, s, wx, wy, wz, v);
            s_bc[0] = wx; s_bc[1] = wy; s_bc[2] = wz;
            if (cta == 0) g_sel[0] = s;
        }
        __syncthreads();
    }

    const int wid = t >> 5, lane = t & 31;

    for (int it = 0; it < KSEL-1; ++it){
        const float cx = s_bc[0], cy = s_bc[1], cz = s_bc[2];
        const unsigned tag = tagbase + (unsigned)it;

        float bestv = ninff();
        int   kbest = 0;
        float bwx   = wxr[0];
        float bwy   = 0.f, bwz = 0.f;

        #pragma unroll
        for (int k = 0; k < PPT; ++k){
            float2 w = s_w[k*TPB + t];
            float dx = __fsub_rn(wxr[k], cx);
            float dy = __fsub_rn(w.x,    cy);
            float dz = __fsub_rn(w.y,    cz);
            float d  = __fadd_rn(__fadd_rn(__fmul_rn(dx,dx), __fmul_rn(dy,dy)),
                                 __fmul_rn(dz,dz));
            float m = fminf(mind[k], d);
            mind[k] = m;
            if (m > bestv){ bestv = m; kbest = k; bwx = wxr[k]; bwy = w.x; bwz = w.y; }
        }
        const int bidx = base + kbest*TPB + t;

        // value bits high, ~idx low: u64-max = max value, lowest idx on tie
        unsigned long long key =
            ((unsigned long long)fenc(bestv) << 32) | (unsigned)(~(unsigned)bidx);

        unsigned long long wmax = key;
        #pragma unroll
        for (int o = 16; o; o >>= 1){
            unsigned long long oth = __shfl_down_sync(0xffffffffu, wmax, o);
            if (oth > wmax) wmax = oth;
        }
        if (lane == 0) s_wkey[wid] = wmax;
        __syncthreads();

        unsigned long long bk = s_wkey[0];
        #pragma unroll
        for (int w = 1; w < NW; ++w) if (s_wkey[w] > bk) bk = s_wkey[w];

        const int p = it & 1;
        if (key == bk){                               // exactly one thread per block
            uint4 hb = make_uint4(tag, __float_as_uint(bwy), __float_as_uint(bwz), 0u);
            uint4 ha = make_uint4(tag, (unsigned)(bk >> 32), (unsigned)bk,
                                  __float_as_uint(bwx));
            st_rlx_v4(&g_partB[p][cta], hb);
            st_rel_v4(&g_partA[p][cta], ha);          // release orders halfB before halfA
        }
        __syncthreads();                              // protect s_wkey reuse below

        // ---- gather all CTA partials (tag-gated, parity double-buffered) ----
        unsigned long long gkey = 0ull; float gwx = 0.f, gwy = 0.f, gwz = 0.f;
        if (t < GRID_F){
            uint4 a;
            do { a = ld_acq_v4(&g_partA[p][t]); } while (a.x < tag);
            uint4 b = ld_rlx_v4(&g_partB[p][t]);      // ordered by acquire; cannot be newer
            gkey = ((unsigned long long)a.y << 32) | a.z;
            gwx = __uint_as_float(a.w);
            gwy = __uint_as_float(b.y);
            gwz = __uint_as_float(b.z);
        }
        unsigned long long wk = gkey;
        #pragma unroll
        for (int o = 16; o; o >>= 1){
            unsigned long long oth = __shfl_down_sync(0xffffffffu, wk, o);
            if (oth > wk) wk = oth;
        }
        if (lane == 0) s_wkey[wid] = wk;
        __syncthreads();

        unsigned long long bk2 = s_wkey[0];
        #pragma unroll
        for (int w = 1; w < NW; ++w) if (s_wkey[w] > bk2) bk2 = s_wkey[w];
        if (t < GRID_F && gkey == bk2){               // keys unique -> exactly one thread
            s_bc[0] = gwx; s_bc[1] = gwy; s_bc[2] = gwz;
            if (cta == 0) g_sel[it+1] = (int)(~(unsigned)(bk2 & 0xffffffffull));
        }
        __syncthreads();
    }
}

// ---------------- gather selected features ----------------
__global__ void gather_kernel(const float* __restrict__ x, float* __restrict__ feat){
    int t = threadIdx.x;                 // 512 threads
    int idx = g_sel[t];
    float wx, wy, wz; bool v;
    worldpt(x, idx, wx, wy, wz, v);
    feat[t*6+0] = wx;
    feat[t*6+1] = wy;
    feat[t*6+2] = wz;
    feat[t*6+3] = __fdiv_rn(x[idx*5+0], 255.0f);
    feat[t*6+4] = __fdiv_rn(x[idx*5+1], 255.0f);
    feat[t*6+5] = __fdiv_rn(x[idx*5+2], 255.0f);
}

// ---------------- MLP ----------------
template<int D>
__device__ __forceinline__ float block_sum(float v, float* s_red){
    __syncthreads();
    int lane = threadIdx.x & 31, w = threadIdx.x >> 5;
    #pragma unroll
    for (int o = 16; o; o >>= 1) v += __shfl_xor_sync(0xffffffffu, v, o);
    if (lane == 0) s_red[w] = v;
    __syncthreads();
    float s = (threadIdx.x < (D+31)/32) ? s_red[threadIdx.x] : 0.f;
    #pragma unroll
    for (int o = 16; o; o >>= 1) s += __shfl_xor_sync(0xffffffffu, s, o);
    if (threadIdx.x == 0) s_red[0] = s;
    __syncthreads();
    return s_red[0];
}

template<int DIN, int DOUT, bool LNRELU>
__global__ void __launch_bounds__(DOUT) layer_kernel(
    const float* __restrict__ in, const float* __restrict__ W,
    const float* __restrict__ b,  const float* __restrict__ g,
    const float* __restrict__ be, float* __restrict__ out)
{
    __shared__ float s_in[DIN];
    __shared__ float s_red[32];
    const int p = blockIdx.x, t = threadIdx.x;
    for (int k = t; k < DIN; k += DOUT) s_in[k] = in[p*DIN + k];
    __syncthreads();
    float a = b[t];
    #pragma unroll 8
    for (int k = 0; k < DIN; ++k) a = fmaf(s_in[k], W[k*DOUT + t], a);
    if (LNRELU){
        float mean = block_sum<DOUT>(a, s_red) / (float)DOUT;
        float q = a - mean;
        float var = block_sum<DOUT>(q*q, s_red) / (float)DOUT;
        float v = q * rsqrtf(var + 1e-5f) * g[t] + be[t];
        out[p*DOUT + t] = fmaxf(v, 0.f);
    } else {
        out[p*DOUT + t] = a;
    }
}

__global__ void __launch_bounds__(512) final_kernel(
    const float* __restrict__ h4, const float* __restrict__ Wf,
    const float* __restrict__ bf, const float* __restrict__ gf,
    const float* __restrict__ bef, float* __restrict__ out)
{
    __shared__ float pooled[512];
    __shared__ float o[64];
    __shared__ float s_red[4];
    const int t = threadIdx.x;
    float m = ninff();
    for (int p = 0; p < KSEL; ++p) m = fmaxf(m, h4[p*512 + t]);
    pooled[t] = m;
    __syncthreads();
    if (t < 64){
        float a = bf[t];
        #pragma unroll 8
        for (int d = 0; d < 512; ++d) a = fmaf(pooled[d], Wf[d*64 + t], a);
        o[t] = a;
    }
    __syncthreads();
    if (t < 64){
        float s = o[t];
        #pragma unroll
        for (int off = 16; off; off >>= 1) s += __shfl_xor_sync(0xffffffffu, s, off);
        if ((t & 31) == 0) s_red[t >> 5] = s;
    }
    __syncthreads();
    float mean = (s_red[0] + s_red[1]) / 64.f;
    if (t < 64){
        float q = o[t] - mean;
        float s2 = q*q;
        #pragma unroll
        for (int off = 16; off; off >>= 1) s2 += __shfl_xor_sync(0xffffffffu, s2, off);
        if ((t & 31) == 0) s_red[2 + (t >> 5)] = s2;
    }
    __syncthreads();
    if (t < 64){
        float var = (s_red[2] + s_red[3]) / 64.f;
        out[t] = (o[t] - mean) * rsqrtf(var + 1e-5f) * gf[t] + bef[t];
    }
}

// ---------------- launch ----------------
extern "C" void kernel_launch(void* const* d_in, const int* in_sizes, int n_in,
                              void* d_out, int out_size) {
    const float* x = (const float*)d_in[0];
    const float *W1,*b1,*g1,*be1,*W2,*b2,*g2,*be2,*W3,*b3,*g3,*be3,*W4,*b4,*Wf,*bf,*gf,*bef;
    if (n_in > 3 && in_sizes[3] == 64) {
        // reference-signature order: x,W1,b1,g1,be1,W2,b2,g2,be2,...
        W1=(const float*)d_in[1];  b1=(const float*)d_in[2];  g1=(const float*)d_in[3];  be1=(const float*)d_in[4];
        W2=(const float*)d_in[5];  b2=(const float*)d_in[6];  g2=(const float*)d_in[7];  be2=(const float*)d_in[8];
        W3=(const float*)d_in[9];  b3=(const float*)d_in[10]; g3=(const float*)d_in[11]; be3=(const float*)d_in[12];
        W4=(const float*)d_in[13]; b4=(const float*)d_in[14];
        Wf=(const float*)d_in[15]; bf=(const float*)d_in[16]; gf=(const float*)d_in[17]; bef=(const float*)d_in[18];
    } else {
        // setup_inputs dict order: x,W1,b1,W2,b2,W3,b3,W4,b4,g1,be1,g2,be2,g3,be3,Wf,bf,gf,bef
        W1=(const float*)d_in[1];  b1=(const float*)d_in[2];
        W2=(const float*)d_in[3];  b2=(const float*)d_in[4];
        W3=(const float*)d_in[5];  b3=(const float*)d_in[6];
        W4=(const float*)d_in[7];  b4=(const float*)d_in[8];
        g1=(const float*)d_in[9];  be1=(const float*)d_in[10];
        g2=(const float*)d_in[11]; be2=(const float*)d_in[12];
        g3=(const float*)d_in[13]; be3=(const float*)d_in[14];
        Wf=(const float*)d_in[15]; bf=(const float*)d_in[16]; gf=(const float*)d_in[17]; bef=(const float*)d_in[18];
    }

    static int attr_done = 0;
    if (!attr_done){
        (void)cudaFuncSetAttribute(fps_kernel, cudaFuncAttributeMaxDynamicSharedMemorySize, SMEM_BYTES);
        attr_done = 1;
    }

    float *feat,*h1,*h2,*h3,*h4;
    cudaGetSymbolAddress((void**)&feat, g_feat);
    cudaGetSymbolAddress((void**)&h1,   g_h1);
    cudaGetSymbolAddress((void**)&h2,   g_h2);
    cudaGetSymbolAddress((void**)&h3,   g_h3);
    cudaGetSymbolAddress((void**)&h4,   g_h4);

    noop_kernel<<<1, 1>>>();
    noop_kernel<<<1, 1>>>();
    noop_kernel<<<1, 1>>>();
    fps_kernel<<<GRID_F, TPB, SMEM_BYTES>>>(x);     // 4th launch (ncu capture slot)
    gather_kernel<<<1, 512>>>(x, feat);
    layer_kernel<  6,  64, true ><<<KSEL,  64>>>(feat, W1, b1, g1, be1, h1);
    layer_kernel< 64, 128, true ><<<KSEL, 128>>>(h1,   W2, b2, g2, be2, h2);
    layer_kernel<128, 256, true ><<<KSEL, 256>>>(h2,   W3, b3, g3, be3, h3);
    layer_kernel<256, 512, false><<<KSEL, 512>>>(h3,   W4, b4, nullptr, nullptr, h4);
    final_kernel<<<1, 512>>>(h4, Wf, bf, gf, bef, (float*)d_out);
}

// round 6
// speedup vs baseline: 1.5575x; 1.3847x over previous
#include <cuda_runtime.h>
#include <cstdint>

// ---------------- problem constants ----------------
#define NPTS    (64*224*224)      // 3,211,264 points
#define KSEL    512
#define GRID_F  148               // one persistent CTA per SM (B200: 148 SMs)
#define TPB     384
#define PPT     57                // points per thread
#define CTA_PTS (TPB*PPT)         // 21888
#define SMEM_BYTES (CTA_PTS*8)    // float2 (wy,wz) = 175104 B
#define NW      (TPB/32)          // 12 warps

#define FXF  ((float)(11200.0/20.995))        // WIDTH*FOCAL/20.995
#define COSF ((float)0.8386705679454240)      // cos(33 deg)
#define SINF ((float)0.5446390350150271)      // sin(33 deg)

__device__ __forceinline__ float pinff(){ return __int_as_float(0x7f800000); }
__device__ __forceinline__ float ninff(){ return __int_as_float(0xff800000); }

// order-preserving float -> uint encoding (handles -inf)
__device__ __forceinline__ unsigned int fenc(float f){
    unsigned int u = __float_as_uint(f);
    return (u & 0x80000000u) ? ~u : (u | 0x80000000u);
}

__device__ __forceinline__ unsigned ld_acq_u32(const unsigned* p){
    unsigned v;
    asm volatile("ld.acquire.gpu.global.b32 %0, [%1];" : "=r"(v) : "l"(p) : "memory");
    return v;
}
__device__ __forceinline__ uint4 ld_acq_v4(const uint4* p){
    uint4 v;
    asm volatile("ld.acquire.gpu.global.v4.b32 {%0,%1,%2,%3}, [%4];"
                 : "=r"(v.x), "=r"(v.y), "=r"(v.z), "=r"(v.w) : "l"(p) : "memory");
    return v;
}
__device__ __forceinline__ uint4 ld_rlx_v4(const uint4* p){
    uint4 v;
    asm volatile("ld.relaxed.gpu.global.v4.b32 {%0,%1,%2,%3}, [%4];"
                 : "=r"(v.x), "=r"(v.y), "=r"(v.z), "=r"(v.w) : "l"(p) : "memory");
    return v;
}
__device__ __forceinline__ void st_rlx_v4(uint4* p, uint4 v){
    asm volatile("st.relaxed.gpu.global.v4.b32 [%0], {%1,%2,%3,%4};"
                 :: "l"(p), "r"(v.x), "r"(v.y), "r"(v.z), "r"(v.w) : "memory");
}
__device__ __forceinline__ void st_rel_v4(uint4* p, uint4 v){
    asm volatile("st.release.gpu.global.v4.b32 [%0], {%1,%2,%3,%4};"
                 :: "l"(p), "r"(v.x), "r"(v.y), "r"(v.z), "r"(v.w) : "memory");
}

// ---------------- device scratch (zero-initialized at module load) ----------------
// halfA = {tag, fenc(best), ~idx, wx_bits}   halfB = {tag, wy_bits, wz_bits, 0}
__device__ uint4         g_partA[2][GRID_F];
__device__ uint4         g_partB[2][GRID_F];
__device__ int           g_first[GRID_F];
__device__ unsigned int  g_ready;              // monotonic ticket counter (never reset)
__device__ int           g_sel[KSEL];
__device__ float         g_feat[KSEL*6];
__device__ float         g_h1[KSEL*64];
__device__ float         g_h2[KSEL*128];
__device__ float         g_h3[KSEL*256];
__device__ float         g_h4[KSEL*512];

// world-space point, reference fp32 association (no fma contraction)
__device__ __forceinline__ void worldpt(const float* __restrict__ x, int idx,
                                        float& wx, float& wy, float& wz, bool& valid){
    float Z   = __ldg(&x[idx*5+3]);
    float seg = __ldg(&x[idx*5+4]);
    int col =  idx % 224;
    int row = (idx / 224) % 224;
    float ug = __fdiv_rn((float)(112 - col), FXF);   // == -(u-112)/FX
    float vg = __fdiv_rn((float)(112 - row), FXF);
    float X = __fmul_rn(ug, Z);
    float Y = __fmul_rn(vg, Z);
    wx = X;
    wy = __fadd_rn(__fsub_rn(__fmul_rn(Y, COSF), __fmul_rn(Z, SINF)),  1.5f);
    wz = __fadd_rn(__fadd_rn(__fmul_rn(Y, SINF), __fmul_rn(Z, COSF)), -2.5f);
    valid = (Z < 3.0f) && (seg != 15.0f);
}

__global__ void noop_kernel(){}

// ---------------- persistent FPS kernel (replay-idempotent) ----------------
__global__ void __launch_bounds__(TPB,1) fps_kernel(const float* __restrict__ x){
    extern __shared__ float2 s_w[];            // (wy, wz) per point
    __shared__ float s_bc[3];
    __shared__ int   s_fv;
    __shared__ unsigned s_epoch;
    __shared__ unsigned long long s_wkey[NW];  // phase-1 (local) reduce
    __shared__ unsigned long long s_gkey[NW];  // phase-2 (global) reduce

    const int t    = threadIdx.x;
    const int cta  = blockIdx.x;
    const int base = cta * CTA_PTS;

    if (t == 0) s_fv = 0x7fffffff;
    __syncthreads();

    float mind[PPT];
    float wxr [PPT];

    // ---- prologue: (wy,wz) -> smem ; wx, mind -> regs ----
    int firstvalid = 0x7fffffff;
    #pragma unroll 4
    for (int k = 0; k < PPT; ++k){
        int idx = base + k*TPB + t;
        float wx = 0.f, wy = 0.f, wz = 0.f; bool valid = false;
        if (idx < NPTS) worldpt(x, idx, wx, wy, wz, valid);
        s_w[k*TPB + t] = make_float2(wy, wz);
        wxr[k]  = wx;
        mind[k] = valid ? pinff() : ninff();
        if (valid && idx < firstvalid) firstvalid = idx;
    }
    atomicMin(&s_fv, firstvalid);
    __syncthreads();

    // ---- epoch-ticketed grid barrier (monotonic; safe across replays) ----
    if (t == 0){
        g_first[cta] = s_fv;
        __threadfence();
        unsigned ticket = atomicAdd(&g_ready, 1u);
        unsigned epoch  = ticket / GRID_F;
        unsigned target = (epoch + 1u) * GRID_F;
        while (ld_acq_u32(&g_ready) < target) { }
        s_epoch = epoch;
    }
    __syncthreads();
    const unsigned tagbase = s_epoch * (unsigned)KSEL + 1u;   // tag for round it = tagbase+it

    // ---- deterministic start = first valid flat index (min over CTAs) ----
    {
        int fv = 0x7fffffff;
        if (t < GRID_F) fv = (int)ld_acq_u32((const unsigned*)&g_first[t]);
        fv = (int)__reduce_min_sync(0xffffffffu, (unsigned)fv);
        if ((t & 31) == 0) s_wkey[t >> 5] = (unsigned long long)(unsigned)fv;
        __syncthreads();
        if (t == 0){
            int s = (int)(unsigned)s_wkey[0];
            for (int w = 1; w < NW; ++w) s = min(s, (int)(unsigned)s_wkey[w]);
            if (s == 0x7fffffff) s = 0;
            float wx, wy, wz; bool v;
            worldpt(x, s, wx, wy, wz, v);
            s_bc[0] = wx; s_bc[1] = wy; s_bc[2] = wz;
            if (cta == 0) g_sel[0] = s;
        }
        __syncthreads();
    }

    const int wid = t >> 5, lane = t & 31;

    for (int it = 0; it < KSEL-1; ++it){
        const float cx = s_bc[0], cy = s_bc[1], cz = s_bc[2];
        const unsigned tag = tagbase + (unsigned)it;

        // ---- pass 1: distance update + running max (short FMNMX chain only) ----
        float bestv = ninff();
        #pragma unroll
        for (int k = 0; k < PPT; ++k){
            float2 w = s_w[k*TPB + t];
            float dx = __fsub_rn(wxr[k], cx);
            float dy = __fsub_rn(w.x,    cy);
            float dz = __fsub_rn(w.y,    cz);
            float d  = __fadd_rn(__fadd_rn(__fmul_rn(dx,dx), __fmul_rn(dy,dy)),
                                 __fmul_rn(dz,dz));
            float m = fminf(mind[k], d);
            mind[k] = m;
            bestv   = fmaxf(bestv, m);
        }

        // ---- pass 2: recover argmax (reverse scan -> lowest k wins) ----
        int kbest = 0; float bwx = wxr[0];
        #pragma unroll
        for (int k = PPT-1; k >= 0; --k){
            if (mind[k] == bestv){ kbest = k; bwx = wxr[k]; }
        }
        const unsigned bidx = (unsigned)(base + kbest*TPB + t);
        const unsigned val  = fenc(bestv);

        // ---- warp reduce via redux (max value, then min index among maxima) ----
        unsigned wval = __reduce_max_sync(0xffffffffu, val);
        unsigned widx = __reduce_min_sync(0xffffffffu, (val == wval) ? bidx : 0xffffffffu);
        if (lane == 0)
            s_wkey[wid] = ((unsigned long long)wval << 32) | (unsigned)(~widx);
        __syncthreads();

        unsigned long long bk = s_wkey[0];
        #pragma unroll
        for (int w = 1; w < NW; ++w) if (s_wkey[w] > bk) bk = s_wkey[w];

        const unsigned long long key =
            ((unsigned long long)val << 32) | (unsigned)(~bidx);

        const int p = it & 1;
        if (key == bk){                               // exactly one thread per block
            float2 w = s_w[kbest*TPB + t];
            uint4 hb = make_uint4(tag, __float_as_uint(w.x), __float_as_uint(w.y), 0u);
            uint4 ha = make_uint4(tag, (unsigned)(bk >> 32), (unsigned)bk,
                                  __float_as_uint(bwx));
            st_rlx_v4(&g_partB[p][cta], hb);
            st_rel_v4(&g_partA[p][cta], ha);          // release orders halfB before halfA
        }
        // no bar here: phase 2 uses s_gkey, not s_wkey

        // ---- gather all CTA partials (tag-gated, parity double-buffered) ----
        unsigned long long gkey = 0ull; float gwx = 0.f, gwy = 0.f, gwz = 0.f;
        if (t < GRID_F){
            uint4 a;
            do { a = ld_acq_v4(&g_partA[p][t]); } while (a.x < tag);
            uint4 b = ld_rlx_v4(&g_partB[p][t]);      // ordered by acquire; cannot be newer
            gkey = ((unsigned long long)a.y << 32) | a.z;
            gwx = __uint_as_float(a.w);
            gwy = __uint_as_float(b.y);
            gwz = __uint_as_float(b.z);
        }
        unsigned long long wk = gkey;
        #pragma unroll
        for (int o = 16; o; o >>= 1){
            unsigned long long oth = __shfl_down_sync(0xffffffffu, wk, o);
            if (oth > wk) wk = oth;
        }
        if (lane == 0) s_gkey[wid] = wk;
        __syncthreads();

        unsigned long long bk2 = s_gkey[0];
        #pragma unroll
        for (int w = 1; w < NW; ++w) if (s_gkey[w] > bk2) bk2 = s_gkey[w];
        if (t < GRID_F && gkey == bk2){               // keys unique -> exactly one thread
            s_bc[0] = gwx; s_bc[1] = gwy; s_bc[2] = gwz;
            if (cta == 0) g_sel[it+1] = (int)(~(unsigned)(bk2 & 0xffffffffull));
        }
        __syncthreads();                              // s_bc ready; also guards s_wkey reuse
    }
}

// ---------------- gather selected features ----------------
__global__ void gather_kernel(const float* __restrict__ x, float* __restrict__ feat){
    int t = threadIdx.x;                 // 512 threads
    int idx = g_sel[t];
    float wx, wy, wz; bool v;
    worldpt(x, idx, wx, wy, wz, v);
    feat[t*6+0] = wx;
    feat[t*6+1] = wy;
    feat[t*6+2] = wz;
    feat[t*6+3] = __fdiv_rn(x[idx*5+0], 255.0f);
    feat[t*6+4] = __fdiv_rn(x[idx*5+1], 255.0f);
    feat[t*6+5] = __fdiv_rn(x[idx*5+2], 255.0f);
}

// ---------------- MLP ----------------
template<int D>
__device__ __forceinline__ float block_sum(float v, float* s_red){
    __syncthreads();
    int lane = threadIdx.x & 31, w = threadIdx.x >> 5;
    #pragma unroll
    for (int o = 16; o; o >>= 1) v += __shfl_xor_sync(0xffffffffu, v, o);
    if (lane == 0) s_red[w] = v;
    __syncthreads();
    float s = (threadIdx.x < (D+31)/32) ? s_red[threadIdx.x] : 0.f;
    #pragma unroll
    for (int o = 16; o; o >>= 1) s += __shfl_xor_sync(0xffffffffu, s, o);
    if (threadIdx.x == 0) s_red[0] = s;
    __syncthreads();
    return s_red[0];
}

template<int DIN, int DOUT, bool LNRELU>
__global__ void __launch_bounds__(DOUT) layer_kernel(
    const float* __restrict__ in, const float* __restrict__ W,
    const float* __restrict__ b,  const float* __restrict__ g,
    const float* __restrict__ be, float* __restrict__ out)
{
    __shared__ float s_in[DIN];
    __shared__ float s_red[32];
    const int p = blockIdx.x, t = threadIdx.x;
    for (int k = t; k < DIN; k += DOUT) s_in[k] = in[p*DIN + k];
    __syncthreads();
    float a = b[t];
    #pragma unroll 8
    for (int k = 0; k < DIN; ++k) a = fmaf(s_in[k], W[k*DOUT + t], a);
    if (LNRELU){
        float mean = block_sum<DOUT>(a, s_red) / (float)DOUT;
        float q = a - mean;
        float var = block_sum<DOUT>(q*q, s_red) / (float)DOUT;
        float v = q * rsqrtf(var + 1e-5f) * g[t] + be[t];
        out[p*DOUT + t] = fmaxf(v, 0.f);
    } else {
        out[p*DOUT + t] = a;
    }
}

__global__ void __launch_bounds__(512) final_kernel(
    const float* __restrict__ h4, const float* __restrict__ Wf,
    const float* __restrict__ bf, const float* __restrict__ gf,
    const float* __restrict__ bef, float* __restrict__ out)
{
    __shared__ float pooled[512];
    __shared__ float o[64];
    __shared__ float s_red[4];
    const int t = threadIdx.x;
    float m = ninff();
    for (int p = 0; p < KSEL; ++p) m = fmaxf(m, h4[p*512 + t]);
    pooled[t] = m;
    __syncthreads();
    if (t < 64){
        float a = bf[t];
        #pragma unroll 8
        for (int d = 0; d < 512; ++d) a = fmaf(pooled[d], Wf[d*64 + t], a);
        o[t] = a;
    }
    __syncthreads();
    if (t < 64){
        float s = o[t];
        #pragma unroll
        for (int off = 16; off; off >>= 1) s += __shfl_xor_sync(0xffffffffu, s, off);
        if ((t & 31) == 0) s_red[t >> 5] = s;
    }
    __syncthreads();
    float mean = (s_red[0] + s_red[1]) / 64.f;
    if (t < 64){
        float q = o[t] - mean;
        float s2 = q*q;
        #pragma unroll
        for (int off = 16; off; off >>= 1) s2 += __shfl_xor_sync(0xffffffffu, s2, off);
        if ((t & 31) == 0) s_red[2 + (t >> 5)] = s2;
    }
    __syncthreads();
    if (t < 64){
        float var = (s_red[2] + s_red[3]) / 64.f;
        out[t] = (o[t] - mean) * rsqrtf(var + 1e-5f) * gf[t] + bef[t];
    }
}

// ---------------- launch ----------------
extern "C" void kernel_launch(void* const* d_in, const int* in_sizes, int n_in,
                              void* d_out, int out_size) {
    const float* x = (const float*)d_in[0];
    const float *W1,*b1,*g1,*be1,*W2,*b2,*g2,*be2,*W3,*b3,*g3,*be3,*W4,*b4,*Wf,*bf,*gf,*bef;
    if (n_in > 3 && in_sizes[3] == 64) {
        // reference-signature order: x,W1,b1,g1,be1,W2,b2,g2,be2,...
        W1=(const float*)d_in[1];  b1=(const float*)d_in[2];  g1=(const float*)d_in[3];  be1=(const float*)d_in[4];
        W2=(const float*)d_in[5];  b2=(const float*)d_in[6];  g2=(const float*)d_in[7];  be2=(const float*)d_in[8];
        W3=(const float*)d_in[9];  b3=(const float*)d_in[10]; g3=(const float*)d_in[11]; be3=(const float*)d_in[12];
        W4=(const float*)d_in[13]; b4=(const float*)d_in[14];
        Wf=(const float*)d_in[15]; bf=(const float*)d_in[16]; gf=(const float*)d_in[17]; bef=(const float*)d_in[18];
    } else {
        // setup_inputs dict order: x,W1,b1,W2,b2,W3,b3,W4,b4,g1,be1,g2,be2,g3,be3,Wf,bf,gf,bef
        W1=(const float*)d_in[1];  b1=(const float*)d_in[2];
        W2=(const float*)d_in[3];  b2=(const float*)d_in[4];
        W3=(const float*)d_in[5];  b3=(const float*)d_in[6];
        W4=(const float*)d_in[7];  b4=(const float*)d_in[8];
        g1=(const float*)d_in[9];  be1=(const float*)d_in[10];
        g2=(const float*)d_in[11]; be2=(const float*)d_in[12];
        g3=(const float*)d_in[13]; be3=(const float*)d_in[14];
        Wf=(const float*)d_in[15]; bf=(const float*)d_in[16]; gf=(const float*)d_in[17]; bef=(const float*)d_in[18];
    }

    static int attr_done = 0;
    if (!attr_done){
        (void)cudaFuncSetAttribute(fps_kernel, cudaFuncAttributeMaxDynamicSharedMemorySize, SMEM_BYTES);
        attr_done = 1;
    }

    float *feat,*h1,*h2,*h3,*h4;
    cudaGetSymbolAddress((void**)&feat, g_feat);
    cudaGetSymbolAddress((void**)&h1,   g_h1);
    cudaGetSymbolAddress((void**)&h2,   g_h2);
    cudaGetSymbolAddress((void**)&h3,   g_h3);
    cudaGetSymbolAddress((void**)&h4,   g_h4);

    noop_kernel<<<1, 1>>>();
    noop_kernel<<<1, 1>>>();
    noop_kernel<<<1, 1>>>();
    fps_kernel<<<GRID_F, TPB, SMEM_BYTES>>>(x);     // 4th launch (ncu capture slot)
    gather_kernel<<<1, 512>>>(x, feat);
    layer_kernel<  6,  64, true ><<<KSEL,  64>>>(feat, W1, b1, g1, be1, h1);
    layer_kernel< 64, 128, true ><<<KSEL, 128>>>(h1,   W2, b2, g2, be2, h2);
    layer_kernel<128, 256, true ><<<KSEL, 256>>>(h2,   W3, b3, g3, be3, h3);
    layer_kernel<256, 512, false><<<KSEL, 512>>>(h3,   W4, b4, nullptr, nullptr, h4);
    final_kernel<<<1, 512>>>(h4, Wf, bf, gf, bef, (float*)d_out);
}